// round 1
// baseline (speedup 1.0000x reference)
#include <cuda_runtime.h>
#include <cstdint>

// Problem constants
#define BB 64
#define TT 512
#define DD 2048
#define FF 128
#define MM (BB * TT)   // 32768

// Scratch (allocation-free rule: __device__ globals)
__device__ float g_energy[BB * TT * FF];  // 16 MB
__device__ float g_alpha [BB * TT * FF];  // 16 MB
__device__ float g_beta  [BB * TT * FF];  // 16 MB

// ---------------------------------------------------------------------------
// Kernel 1: input_energy = X @ W + bias (+left at t=0, +right at t=T-1)
// Tiled fp32 SGEMM: BM=128, BN=128(=F), BK=16, 256 threads, 8x8 per thread.
// ---------------------------------------------------------------------------
__global__ void __launch_bounds__(256) gemm_energy_kernel(
    const float* __restrict__ X,     // [M, D]
    const float* __restrict__ W,     // [D, F]
    const float* __restrict__ bias,  // [F]
    const float* __restrict__ lb,    // [F]
    const float* __restrict__ rb)    // [F]
{
    __shared__ float As[16][128];   // transposed A tile: As[k][m]
    __shared__ float Bs[16][128];   // Bs[k][n]

    const int tid = threadIdx.x;
    const int m0  = blockIdx.x * 128;
    const int ty  = tid >> 4;        // 0..15
    const int tx  = tid & 15;        // 0..15

    // load mapping
    const int aRow = tid >> 2;            // 0..63
    const int aCol = (tid & 3) * 4;       // 0,4,8,12
    const int bRow = tid >> 5;            // 0..7
    const int bCol = (tid & 31) * 4;      // 0..124

    float acc[8][8];
#pragma unroll
    for (int i = 0; i < 8; i++)
#pragma unroll
        for (int j = 0; j < 8; j++) acc[i][j] = 0.f;

    const float* Aptr = X + (size_t)m0 * DD;

    for (int k0 = 0; k0 < DD; k0 += 16) {
        // Load A tile (128 rows x 16 k), store transposed
#pragma unroll
        for (int h = 0; h < 2; h++) {
            const int r = aRow + h * 64;
            float4 v = *(const float4*)(Aptr + (size_t)r * DD + k0 + aCol);
            As[aCol + 0][r] = v.x;
            As[aCol + 1][r] = v.y;
            As[aCol + 2][r] = v.z;
            As[aCol + 3][r] = v.w;
        }
        // Load B tile (16 k x 128 n)
#pragma unroll
        for (int h = 0; h < 2; h++) {
            const int r = bRow + h * 8;
            float4 v = *(const float4*)(W + (size_t)(k0 + r) * FF + bCol);
            *(float4*)&Bs[r][bCol] = v;
        }
        __syncthreads();

#pragma unroll
        for (int kk = 0; kk < 16; kk++) {
            float ra[8], rbv[8];
            *(float4*)&ra[0]  = *(const float4*)&As[kk][ty * 8];
            *(float4*)&ra[4]  = *(const float4*)&As[kk][ty * 8 + 4];
            *(float4*)&rbv[0] = *(const float4*)&Bs[kk][tx * 8];
            *(float4*)&rbv[4] = *(const float4*)&Bs[kk][tx * 8 + 4];
#pragma unroll
            for (int i = 0; i < 8; i++)
#pragma unroll
                for (int j = 0; j < 8; j++)
                    acc[i][j] += ra[i] * rbv[j];
        }
        __syncthreads();
    }

    // Epilogue: + bias, + boundaries
#pragma unroll
    for (int i = 0; i < 8; i++) {
        const int m = m0 + ty * 8 + i;
        const int t = m & (TT - 1);
#pragma unroll
        for (int j = 0; j < 8; j++) {
            const int f = tx * 8 + j;
            float v = acc[i][j] + bias[f];
            if (t == 0)      v += lb[f];
            if (t == TT - 1) v += rb[f];
            g_energy[(size_t)m * FF + f] = v;
        }
    }
}

// ---------------------------------------------------------------------------
// Kernel 2: forward / backward log-space scan.
// One CTA per (batch, direction): grid = 128, block = 128 (thread f).
// new[f] = LSE_i(prev[i] - e[i] - chain[i,f])
//        = S + log( sum_i exp(a[i] - e[i]) * exp(-chain[i,f]) )   [a = prev - S]
// Running scalar shift S (recentered by a[0] each step) keeps exponents
// bounded (|arg| <~ 20) so no per-step max-reduction is needed.
// exp(-chain[:,f]) lives in 128 registers of thread f.
// ---------------------------------------------------------------------------
__global__ void __launch_bounds__(128) scan_kernel(
    const float* __restrict__ chain)   // [F, F]
{
    __shared__ float sE[2][FF];
    __shared__ float sC[2];

    const int f        = threadIdx.x;
    const int b        = blockIdx.x >> 1;
    const int backward = blockIdx.x & 1;

    float creg[FF];
#pragma unroll
    for (int i = 0; i < FF; i++)
        creg[i] = __expf(-chain[i * FF + f]);

    const float* ebase = g_energy + (size_t)b * TT * FF;
    float*       obase = (backward ? g_beta : g_alpha) + (size_t)b * TT * FF;

    int t  = backward ? (TT - 1) : 0;
    const int dt = backward ? -1 : 1;

    float a = 0.f;   // centered prev-alpha
    float S = 0.f;   // scalar shift: true prev = a + S
    float e_cur = ebase[t * FF + f];
    int buf = 0;

    for (int s = 0; s < TT; s++) {
        const int tn = t + dt;
        const float e_next = (s < TT - 1) ? ebase[tn * FF + f] : 0.f;

        const float p = a - e_cur;
        const float E = __expf(p);
        sE[buf][f] = E;
        if (f == 0) sC[buf] = a;
        __syncthreads();

        const float c = sC[buf];
        float a0 = 0.f, a1 = 0.f, a2 = 0.f, a3 = 0.f;
        const float4* E4 = (const float4*)sE[buf];
#pragma unroll
        for (int i = 0; i < 32; i++) {
            const float4 ev = E4[i];
            a0 += ev.x * creg[4 * i + 0];
            a1 += ev.y * creg[4 * i + 1];
            a2 += ev.z * creg[4 * i + 2];
            a3 += ev.w * creg[4 * i + 3];
        }
        const float n = __logf((a0 + a1) + (a2 + a3));

        obase[t * FF + f] = n + S;

        a = n - c;        // recenter
        S += c;
        e_cur = e_next;
        t = tn;
        buf ^= 1;
    }
}

// ---------------------------------------------------------------------------
// Kernel 3: margin = -(alpha[t-1] + e[t] + beta[t+1]); softmax over f.
// One warp per (b,t) row, float4 per lane.
// ---------------------------------------------------------------------------
__global__ void __launch_bounds__(256) margin_softmax_kernel(
    float* __restrict__ out)
{
    const int warp = (blockIdx.x * (blockDim.x >> 5)) + (threadIdx.x >> 5);
    const int lane = threadIdx.x & 31;
    if (warp >= MM) return;

    const int t = warp & (TT - 1);
    const size_t row = (size_t)warp * FF;
    const int f = lane * 4;

    float4 e4 = *(const float4*)(g_energy + row + f);
    float4 a4 = make_float4(0.f, 0.f, 0.f, 0.f);
    float4 b4 = make_float4(0.f, 0.f, 0.f, 0.f);
    if (t > 0)      a4 = *(const float4*)(g_alpha + row - FF + f);
    if (t < TT - 1) b4 = *(const float4*)(g_beta  + row + FF + f);

    float m0 = -(e4.x + a4.x + b4.x);
    float m1 = -(e4.y + a4.y + b4.y);
    float m2 = -(e4.z + a4.z + b4.z);
    float m3 = -(e4.w + a4.w + b4.w);

    float mx = fmaxf(fmaxf(m0, m1), fmaxf(m2, m3));
#pragma unroll
    for (int off = 16; off > 0; off >>= 1)
        mx = fmaxf(mx, __shfl_xor_sync(0xFFFFFFFFu, mx, off));

    float x0 = __expf(m0 - mx);
    float x1 = __expf(m1 - mx);
    float x2 = __expf(m2 - mx);
    float x3 = __expf(m3 - mx);

    float sm = (x0 + x1) + (x2 + x3);
#pragma unroll
    for (int off = 16; off > 0; off >>= 1)
        sm += __shfl_xor_sync(0xFFFFFFFFu, sm, off);

    const float inv = 1.f / sm;
    float4 o;
    o.x = x0 * inv; o.y = x1 * inv; o.z = x2 * inv; o.w = x3 * inv;
    *(float4*)(out + row + f) = o;
}

// ---------------------------------------------------------------------------
extern "C" void kernel_launch(void* const* d_in, const int* in_sizes, int n_in,
                              void* d_out, int out_size)
{
    const float* X     = (const float*)d_in[0];  // [B,T,D]
    const float* W     = (const float*)d_in[1];  // [D,F]
    const float* chain = (const float*)d_in[2];  // [F,F]
    const float* bias  = (const float*)d_in[3];  // [F]
    const float* lb    = (const float*)d_in[4];  // [F]
    const float* rb    = (const float*)d_in[5];  // [F]
    float* out = (float*)d_out;

    gemm_energy_kernel<<<MM / 128, 256>>>(X, W, bias, lb, rb);
    scan_kernel<<<BB * 2, 128>>>(chain);
    margin_softmax_kernel<<<MM / 8, 256>>>(out);
}

// round 4
// speedup vs baseline: 1.6002x; 1.6002x over previous
#include <cuda_runtime.h>
#include <cuda_fp16.h>
#include <cstdint>

// Problem constants
#define BB 64
#define TT 512
#define DD 2048
#define FF 128
#define MM (BB * TT)   // 32768

// Scratch (allocation-free rule: __device__ globals)
__device__ float g_energy[BB * TT * FF];   // 16 MB
__device__ float g_alpha [BB * TT * FF];   // 16 MB
__device__ float g_beta  [BB * TT * FF];   // 16 MB
// W^T split into fp16 hi/lo, pre-laid-out per 32-K chunk: for each f (row) and
// chunk c: 64 halves = [32 hi | 32 lo] = one 128B smem line.
__device__ __half g_Wt[FF * DD * 2];       // 1 MB

// ---------------------------------------------------------------------------
// helpers
// ---------------------------------------------------------------------------
__device__ __forceinline__ uint32_t smem_u32(const void* p) {
    uint32_t a;
    asm("{ .reg .u64 t; cvta.to.shared.u64 t, %1; cvt.u32.u64 %0, t; }" : "=r"(a) : "l"(p));
    return a;
}
#define LDSM4(r0, r1, r2, r3, addr) \
    asm volatile("ldmatrix.sync.aligned.m8n8.x4.shared.b16 {%0,%1,%2,%3}, [%4];" \
                 : "=r"(r0), "=r"(r1), "=r"(r2), "=r"(r3) : "r"(addr))
#define MMA16816(c0, c1, c2, c3, a0, a1, a2, a3, b0, b1) \
    asm volatile("mma.sync.aligned.m16n8k16.row.col.f32.f16.f16.f32 " \
                 "{%0,%1,%2,%3}, {%4,%5,%6,%7}, {%8,%9}, {%0,%1,%2,%3};" \
                 : "+f"(c0), "+f"(c1), "+f"(c2), "+f"(c3) \
                 : "r"(a0), "r"(a1), "r"(a2), "r"(a3), "r"(b0), "r"(b1))

__device__ __forceinline__ uint32_t h2pack(float x, float y) {
    __half2 h = __floats2half2_rn(x, y);
    return *(uint32_t*)&h;
}

// ---------------------------------------------------------------------------
// Kernel 0: transpose + fp16 hi/lo split of W -> g_Wt chunk layout
// ---------------------------------------------------------------------------
__global__ void __launch_bounds__(256) wconv_kernel(const float* __restrict__ W) {
    int i = blockIdx.x * 256 + threadIdx.x;   // linear over W [k][f], coalesced
    int f = i & (FF - 1);
    int k = i >> 7;
    float x = W[i];
    __half hi = __float2half_rn(x);
    __half lo = __float2half_rn(x - __half2float(hi));
    int c  = k >> 5;
    int kl = k & 31;
    int base = f * (DD * 2) + c * 64 + kl;
    g_Wt[base]      = hi;
    g_Wt[base + 32] = lo;
}

// ---------------------------------------------------------------------------
// Kernel 1: energy = X @ W + bias (+lb at t=0, +rb at t=T-1)
// mma.sync fp16 hi/lo split (3 products, shared fp32 accumulators).
// BM=128, BN=128, BK=32; 256 threads = 8 warps (2 M x 4 N), warp tile 64x32.
// SMEM per stage: A 128x128B (k hi|lo interleaved) + B 128x128B = 32KB; x2 stages.
// ---------------------------------------------------------------------------
#define STAGE_BYTES 32768
#define SMEM_DYN (2 * STAGE_BYTES)
#define NCHUNK (DD / 32)   // 64

__global__ void __launch_bounds__(256) gemm_mma_kernel(
    const float* __restrict__ X,     // [M, D]
    const float* __restrict__ bias,  // [F]
    const float* __restrict__ lb,    // [F]
    const float* __restrict__ rb)    // [F]
{
    extern __shared__ __align__(128) char smem[];
    const uint32_t sbase = smem_u32(smem);

    const int tid = threadIdx.x;
    const int wid = tid >> 5;
    const int L   = tid & 31;
    const int m0  = blockIdx.x * 128;

    const int warp_m = wid & 1;        // 0..1  -> m offset 0/64
    const int warp_n = wid >> 1;       // 0..3  -> n offset 0/32/64/96

    // ---- loader mapping: row = tid>>1 (0..127), h = tid&1 ----
    const int lrow = tid >> 1;
    const int lh   = tid & 1;
    const float*  xsrc = X + (size_t)(m0 + lrow) * DD + lh * 16;
    const __half* wsrc = g_Wt + (size_t)lrow * (DD * 2) + lh * 32;

    // smem byte offsets for this thread's stores (swizzled 16B units)
    const int arow_b = lrow * 128;
    const int sx = lrow & 7;
    // A units: hi -> lh*2, lh*2+1 ; lo -> 4+lh*2, 4+lh*2+1
    uint32_t aoff[4], boff[4];
#pragma unroll
    for (int u = 0; u < 2; u++) {
        aoff[u]     = arow_b + (((lh * 2 + u)     ^ sx) * 16);
        aoff[2 + u] = arow_b + (((4 + lh * 2 + u) ^ sx) * 16);
    }
#pragma unroll
    for (int u = 0; u < 4; u++)
        boff[u] = 16384 + arow_b + (((lh * 4 + u) ^ sx) * 16);

    // ---- ldmatrix lane address components ----
    // A frags: row = warp_m*64 + mf*16 + (L&15); unit = ks*2 + (L>>4) + part*4
    const int arow_l = warp_m * 64 + (L & 15);
    const int a_us   = (L >> 4);          // unit select
    const int lxor   = (L & 7);
    // B frags: row = warp_n*32 + nfp*16 + (L&7) + ((L>>4)<<3); unit = ks*2 + ((L>>3)&1) + part*4
    const int brow_l = warp_n * 32 + (L & 7) + ((L >> 4) << 3);
    const int b_us   = ((L >> 3) & 1);

    float c0[4][4], c1[4][4], c2[4][4], c3[4][4];
#pragma unroll
    for (int i = 0; i < 4; i++)
#pragma unroll
        for (int j = 0; j < 4; j++) { c0[i][j] = 0.f; c1[i][j] = 0.f; c2[i][j] = 0.f; c3[i][j] = 0.f; }

    // ---- preload chunk 0 ----
    float4 av0 = *(const float4*)(xsrc + 0);
    float4 av1 = *(const float4*)(xsrc + 4);
    float4 av2 = *(const float4*)(xsrc + 8);
    float4 av3 = *(const float4*)(xsrc + 12);
    uint4 bv0 = *(const uint4*)(wsrc + 0);
    uint4 bv1 = *(const uint4*)(wsrc + 8);
    uint4 bv2 = *(const uint4*)(wsrc + 16);
    uint4 bv3 = *(const uint4*)(wsrc + 24);

    // store chunk 0 into stage 0
    {
        char* st = smem;
        uint4 h0, h1, l0v, l1v;
        h0.x = h2pack(av0.x, av0.y); h0.y = h2pack(av0.z, av0.w);
        h0.z = h2pack(av1.x, av1.y); h0.w = h2pack(av1.z, av1.w);
        h1.x = h2pack(av2.x, av2.y); h1.y = h2pack(av2.z, av2.w);
        h1.z = h2pack(av3.x, av3.y); h1.w = h2pack(av3.z, av3.w);
        l0v.x = h2pack(av0.x - __half2float(__float2half_rn(av0.x)), av0.y - __half2float(__float2half_rn(av0.y)));
        l0v.y = h2pack(av0.z - __half2float(__float2half_rn(av0.z)), av0.w - __half2float(__float2half_rn(av0.w)));
        l0v.z = h2pack(av1.x - __half2float(__float2half_rn(av1.x)), av1.y - __half2float(__float2half_rn(av1.y)));
        l0v.w = h2pack(av1.z - __half2float(__float2half_rn(av1.z)), av1.w - __half2float(__float2half_rn(av1.w)));
        l1v.x = h2pack(av2.x - __half2float(__float2half_rn(av2.x)), av2.y - __half2float(__float2half_rn(av2.y)));
        l1v.y = h2pack(av2.z - __half2float(__float2half_rn(av2.z)), av2.w - __half2float(__float2half_rn(av2.w)));
        l1v.z = h2pack(av3.x - __half2float(__float2half_rn(av3.x)), av3.y - __half2float(__float2half_rn(av3.y)));
        l1v.w = h2pack(av3.z - __half2float(__float2half_rn(av3.z)), av3.w - __half2float(__float2half_rn(av3.w)));
        *(uint4*)(st + aoff[0]) = h0;
        *(uint4*)(st + aoff[1]) = h1;
        *(uint4*)(st + aoff[2]) = l0v;
        *(uint4*)(st + aoff[3]) = l1v;
        *(uint4*)(st + boff[0]) = bv0;
        *(uint4*)(st + boff[1]) = bv1;
        *(uint4*)(st + boff[2]) = bv2;
        *(uint4*)(st + boff[3]) = bv3;
    }
    __syncthreads();

    for (int c = 0; c < NCHUNK; c++) {
        const int stage = c & 1;
        const uint32_t sA = sbase + stage * STAGE_BYTES;
        const uint32_t sB = sA + 16384;

        // prefetch chunk c+1 into registers
        if (c < NCHUNK - 1) {
            const float*  xs = xsrc + (c + 1) * 32;
            const __half* ws = wsrc + (c + 1) * 64;
            av0 = *(const float4*)(xs + 0);
            av1 = *(const float4*)(xs + 4);
            av2 = *(const float4*)(xs + 8);
            av3 = *(const float4*)(xs + 12);
            bv0 = *(const uint4*)(ws + 0);
            bv1 = *(const uint4*)(ws + 8);
            bv2 = *(const uint4*)(ws + 16);
            bv3 = *(const uint4*)(ws + 24);
        }

        // ---- MMA on current stage ----
#pragma unroll
        for (int ks = 0; ks < 2; ks++) {
            uint32_t ahi[4][4], alo[4][4], bhi[4][2], blo[4][2];
#pragma unroll
            for (int mf = 0; mf < 4; mf++) {
                const int r = arow_l + mf * 16;
                uint32_t ah = sA + r * 128 + (((ks * 2 + a_us)     ^ lxor) * 16);
                uint32_t al = sA + r * 128 + (((4 + ks * 2 + a_us) ^ lxor) * 16);
                LDSM4(ahi[mf][0], ahi[mf][1], ahi[mf][2], ahi[mf][3], ah);
                LDSM4(alo[mf][0], alo[mf][1], alo[mf][2], alo[mf][3], al);
            }
#pragma unroll
            for (int nfp = 0; nfp < 2; nfp++) {
                const int r = brow_l + nfp * 16;
                uint32_t bh = sB + r * 128 + (((ks * 2 + b_us)     ^ lxor) * 16);
                uint32_t bl = sB + r * 128 + (((4 + ks * 2 + b_us) ^ lxor) * 16);
                uint32_t t0, t1, t2, t3;
                LDSM4(t0, t1, t2, t3, bh);
                bhi[nfp * 2][0] = t0; bhi[nfp * 2][1] = t1;
                bhi[nfp * 2 + 1][0] = t2; bhi[nfp * 2 + 1][1] = t3;
                LDSM4(t0, t1, t2, t3, bl);
                blo[nfp * 2][0] = t0; blo[nfp * 2][1] = t1;
                blo[nfp * 2 + 1][0] = t2; blo[nfp * 2 + 1][1] = t3;
            }
#pragma unroll
            for (int mf = 0; mf < 4; mf++)
#pragma unroll
                for (int nf = 0; nf < 4; nf++) {
                    MMA16816(c0[mf][nf], c1[mf][nf], c2[mf][nf], c3[mf][nf],
                             ahi[mf][0], ahi[mf][1], ahi[mf][2], ahi[mf][3],
                             bhi[nf][0], bhi[nf][1]);
                    MMA16816(c0[mf][nf], c1[mf][nf], c2[mf][nf], c3[mf][nf],
                             alo[mf][0], alo[mf][1], alo[mf][2], alo[mf][3],
                             bhi[nf][0], bhi[nf][1]);
                    MMA16816(c0[mf][nf], c1[mf][nf], c2[mf][nf], c3[mf][nf],
                             ahi[mf][0], ahi[mf][1], ahi[mf][2], ahi[mf][3],
                             blo[nf][0], blo[nf][1]);
                }
        }

        // ---- store prefetched chunk into other stage ----
        if (c < NCHUNK - 1) {
            char* st = smem + ((c + 1) & 1) * STAGE_BYTES;
            uint4 h0, h1, l0v, l1v;
            h0.x = h2pack(av0.x, av0.y); h0.y = h2pack(av0.z, av0.w);
            h0.z = h2pack(av1.x, av1.y); h0.w = h2pack(av1.z, av1.w);
            h1.x = h2pack(av2.x, av2.y); h1.y = h2pack(av2.z, av2.w);
            h1.z = h2pack(av3.x, av3.y); h1.w = h2pack(av3.z, av3.w);
            l0v.x = h2pack(av0.x - __half2float(__float2half_rn(av0.x)), av0.y - __half2float(__float2half_rn(av0.y)));
            l0v.y = h2pack(av0.z - __half2float(__float2half_rn(av0.z)), av0.w - __half2float(__float2half_rn(av0.w)));
            l0v.z = h2pack(av1.x - __half2float(__float2half_rn(av1.x)), av1.y - __half2float(__float2half_rn(av1.y)));
            l0v.w = h2pack(av1.z - __half2float(__float2half_rn(av1.z)), av1.w - __half2float(__float2half_rn(av1.w)));
            l1v.x = h2pack(av2.x - __half2float(__float2half_rn(av2.x)), av2.y - __half2float(__float2half_rn(av2.y)));
            l1v.y = h2pack(av2.z - __half2float(__float2half_rn(av2.z)), av2.w - __half2float(__float2half_rn(av2.w)));
            l1v.z = h2pack(av3.x - __half2float(__float2half_rn(av3.x)), av3.y - __half2float(__float2half_rn(av3.y)));
            l1v.w = h2pack(av3.z - __half2float(__float2half_rn(av3.z)), av3.w - __half2float(__float2half_rn(av3.w)));
            *(uint4*)(st + aoff[0]) = h0;
            *(uint4*)(st + aoff[1]) = h1;
            *(uint4*)(st + aoff[2]) = l0v;
            *(uint4*)(st + aoff[3]) = l1v;
            *(uint4*)(st + boff[0]) = bv0;
            *(uint4*)(st + boff[1]) = bv1;
            *(uint4*)(st + boff[2]) = bv2;
            *(uint4*)(st + boff[3]) = bv3;
        }
        __syncthreads();
    }

    // ---- Epilogue ----
#pragma unroll
    for (int nf = 0; nf < 4; nf++) {
        const int f = warp_n * 32 + nf * 8 + (L & 3) * 2;
        const float bx = bias[f], by = bias[f + 1];
        const float lx = lb[f],   ly = lb[f + 1];
        const float rx = rb[f],   ry = rb[f + 1];
#pragma unroll
        for (int mf = 0; mf < 4; mf++) {
            const int mA = m0 + warp_m * 64 + mf * 16 + (L >> 2);
            const int mB = mA + 8;
            const int tA = mA & (TT - 1);
            const int tB = mB & (TT - 1);
            float2 oA, oB;
            oA.x = c0[mf][nf] + bx; oA.y = c1[mf][nf] + by;
            oB.x = c2[mf][nf] + bx; oB.y = c3[mf][nf] + by;
            if (tA == 0)      { oA.x += lx; oA.y += ly; }
            if (tA == TT - 1) { oA.x += rx; oA.y += ry; }
            if (tB == 0)      { oB.x += lx; oB.y += ly; }
            if (tB == TT - 1) { oB.x += rx; oB.y += ry; }
            *(float2*)(g_energy + (size_t)mA * FF + f) = oA;
            *(float2*)(g_energy + (size_t)mB * FF + f) = oB;
        }
    }
}

// ---------------------------------------------------------------------------
// Kernel 2: forward / backward log-space scan (proven in R1).
// ---------------------------------------------------------------------------
__global__ void __launch_bounds__(128) scan_kernel(
    const float* __restrict__ chain)   // [F, F]
{
    __shared__ float sE[2][FF];
    __shared__ float sC[2];

    const int f        = threadIdx.x;
    const int b        = blockIdx.x >> 1;
    const int backward = blockIdx.x & 1;

    float creg[FF];
#pragma unroll
    for (int i = 0; i < FF; i++)
        creg[i] = __expf(-chain[i * FF + f]);

    const float* ebase = g_energy + (size_t)b * TT * FF;
    float*       obase = (backward ? g_beta : g_alpha) + (size_t)b * TT * FF;

    int t  = backward ? (TT - 1) : 0;
    const int dt = backward ? -1 : 1;

    float a = 0.f;   // centered prev-alpha
    float S = 0.f;   // scalar shift
    float e_cur = ebase[t * FF + f];
    int buf = 0;

    for (int s = 0; s < TT; s++) {
        const int tn = t + dt;
        const float e_next = (s < TT - 1) ? ebase[tn * FF + f] : 0.f;

        const float E = __expf(a - e_cur);
        sE[buf][f] = E;
        if (f == 0) sC[buf] = a;
        __syncthreads();

        const float c = sC[buf];
        float a0 = 0.f, a1 = 0.f, a2 = 0.f, a3 = 0.f;
        const float4* E4 = (const float4*)sE[buf];
#pragma unroll
        for (int i = 0; i < 32; i++) {
            const float4 ev = E4[i];
            a0 += ev.x * creg[4 * i + 0];
            a1 += ev.y * creg[4 * i + 1];
            a2 += ev.z * creg[4 * i + 2];
            a3 += ev.w * creg[4 * i + 3];
        }
        const float n = __logf((a0 + a1) + (a2 + a3));

        obase[t * FF + f] = n + S;

        a = n - c;
        S += c;
        e_cur = e_next;
        t = tn;
        buf ^= 1;
    }
}

// ---------------------------------------------------------------------------
// Kernel 3: margin + softmax. One warp per (b,t) row.
// ---------------------------------------------------------------------------
__global__ void __launch_bounds__(256) margin_softmax_kernel(
    float* __restrict__ out)
{
    const int warp = (blockIdx.x * (blockDim.x >> 5)) + (threadIdx.x >> 5);
    const int lane = threadIdx.x & 31;
    if (warp >= MM) return;

    const int t = warp & (TT - 1);
    const size_t row = (size_t)warp * FF;
    const int f = lane * 4;

    float4 e4 = *(const float4*)(g_energy + row + f);
    float4 a4 = make_float4(0.f, 0.f, 0.f, 0.f);
    float4 b4 = make_float4(0.f, 0.f, 0.f, 0.f);
    if (t > 0)      a4 = *(const float4*)(g_alpha + row - FF + f);
    if (t < TT - 1) b4 = *(const float4*)(g_beta  + row + FF + f);

    float m0 = -(e4.x + a4.x + b4.x);
    float m1 = -(e4.y + a4.y + b4.y);
    float m2 = -(e4.z + a4.z + b4.z);
    float m3 = -(e4.w + a4.w + b4.w);

    float mx = fmaxf(fmaxf(m0, m1), fmaxf(m2, m3));
#pragma unroll
    for (int off = 16; off > 0; off >>= 1)
        mx = fmaxf(mx, __shfl_xor_sync(0xFFFFFFFFu, mx, off));

    float x0 = __expf(m0 - mx);
    float x1 = __expf(m1 - mx);
    float x2 = __expf(m2 - mx);
    float x3 = __expf(m3 - mx);

    float sm = (x0 + x1) + (x2 + x3);
#pragma unroll
    for (int off = 16; off > 0; off >>= 1)
        sm += __shfl_xor_sync(0xFFFFFFFFu, sm, off);

    const float inv = 1.f / sm;
    float4 o;
    o.x = x0 * inv; o.y = x1 * inv; o.z = x2 * inv; o.w = x3 * inv;
    *(float4*)(out + row + f) = o;
}

// ---------------------------------------------------------------------------
extern "C" void kernel_launch(void* const* d_in, const int* in_sizes, int n_in,
                              void* d_out, int out_size)
{
    const float* X     = (const float*)d_in[0];  // [B,T,D]
    const float* W     = (const float*)d_in[1];  // [D,F]
    const float* chain = (const float*)d_in[2];  // [F,F]
    const float* bias  = (const float*)d_in[3];  // [F]
    const float* lb    = (const float*)d_in[4];  // [F]
    const float* rb    = (const float*)d_in[5];  // [F]
    float* out = (float*)d_out;

    cudaFuncSetAttribute(gemm_mma_kernel,
                         cudaFuncAttributeMaxDynamicSharedMemorySize, SMEM_DYN);

    wconv_kernel<<<(FF * DD) / 256, 256>>>(W);
    gemm_mma_kernel<<<MM / 128, 256, SMEM_DYN>>>(X, bias, lb, rb);
    scan_kernel<<<BB * 2, 128>>>(chain);
    margin_softmax_kernel<<<MM / 8, 256>>>(out);
}